// round 1
// baseline (speedup 1.0000x reference)
#include <cuda_runtime.h>
#include <math.h>

// Problem constants
#define BDIM   4
#define TDIM   4096
#define DDIM   2048
#define DBDIM  512
#define BT     (BDIM * TDIM)   // 16384 tokens
#define EPSV   1e-6f

// ---------------- scratch (static device globals; no runtime allocation) ----
__device__ float g_z [(size_t)BT * DBDIM];        //  33.5 MB  bottleneck proj
__device__ float g_u [(size_t)BT * 3 * DBDIM];    // 100.7 MB  shifted/masked features
__device__ float g_y [(size_t)BT * DBDIM];        //  33.5 MB  mixed
__device__ float g_k [(size_t)BT * DDIM];         // 134.2 MB  key proj
__device__ float g_v [(size_t)BT * DDIM];         // 134.2 MB  value proj
__device__ float g_n [(size_t)BT * DDIM];         // 134.2 MB  rms(gated out)
__device__ float g_wc[(size_t)DBDIM * 3 * DBDIM]; //   3.1 MB  combined mix weights

// ---------------------------------------------------------------------------
// Combine W_mix[3,512,512] into Wcomb[512,1536]:
//   block0 (shifts 0,1): W2/6 + W3/9 + W4/12
//   block1 (shift 2):    W3/9 + W4/12
//   block2 (shift 3):    W4/12
// (1/(3*order) folded in; y/len(ORDERS) folded in)
// ---------------------------------------------------------------------------
__global__ void combine_wmix(const float* __restrict__ wmix, float* __restrict__ wc) {
    int idx = blockIdx.x * blockDim.x + threadIdx.x;      // f*512 + e
    if (idx >= DBDIM * DBDIM) return;
    int f = idx / DBDIM, e = idx % DBDIM;
    float w2 = wmix[0 * DBDIM * DBDIM + idx];
    float w3 = wmix[1 * DBDIM * DBDIM + idx];
    float w4 = wmix[2 * DBDIM * DBDIM + idx];
    const float c2 = 1.0f / 6.0f, c3 = 1.0f / 9.0f, c4 = 1.0f / 12.0f;
    wc[(size_t)f * 1536 + e]        = w2 * c2 + w3 * c3 + w4 * c4;
    wc[(size_t)f * 1536 + 512 + e]  = w3 * c3 + w4 * c4;
    wc[(size_t)f * 1536 + 1024 + e] = w4 * c4;
}

// ---------------------------------------------------------------------------
// NT SGEMM: C[M,N] = A[M,K] * W[N,K]^T   (both operands K-contiguous)
// 128x128x16 tile, 8x8 per thread, 256 threads. All dims are multiples of
// the tile sizes for every launch in this problem, so no bounds checks.
// ---------------------------------------------------------------------------
#define GBM 128
#define GBN 128
#define GBK 16
#define GTM 8
#define GTN 8

__global__ __launch_bounds__(256, 2)
void sgemm_nt(const float* __restrict__ A, const float* __restrict__ W,
              float* __restrict__ C, int M, int N, int K) {
    __shared__ float As[GBK][GBM];
    __shared__ float Bs[GBK][GBN];

    const int tid = threadIdx.x;
    const int tx  = tid % 16;          // column group (N)
    const int ty  = tid / 16;          // row group (M)
    const int bm  = blockIdx.y * GBM;
    const int bn  = blockIdx.x * GBN;

    const int lr = tid / 4;            // load row 0..63 (+64)
    const int lc = (tid % 4) * 4;      // load col 0,4,8,12

    const float* Ap = A + (size_t)bm * K;
    const float* Wp = W + (size_t)bn * K;

    float acc[GTM][GTN] = {};
    float ra[GTM], rb[GTN];

    for (int k0 = 0; k0 < K; k0 += GBK) {
        #pragma unroll
        for (int r = 0; r < 2; r++) {
            int row = lr + r * 64;
            float4 va = *(const float4*)(Ap + (size_t)row * K + k0 + lc);
            As[lc + 0][row] = va.x; As[lc + 1][row] = va.y;
            As[lc + 2][row] = va.z; As[lc + 3][row] = va.w;
            float4 vb = *(const float4*)(Wp + (size_t)row * K + k0 + lc);
            Bs[lc + 0][row] = vb.x; Bs[lc + 1][row] = vb.y;
            Bs[lc + 2][row] = vb.z; Bs[lc + 3][row] = vb.w;
        }
        __syncthreads();

        #pragma unroll
        for (int kk = 0; kk < GBK; kk++) {
            #pragma unroll
            for (int i = 0; i < GTM; i += 4) {
                float4 t4 = *(const float4*)&As[kk][ty * GTM + i];
                ra[i] = t4.x; ra[i + 1] = t4.y; ra[i + 2] = t4.z; ra[i + 3] = t4.w;
            }
            #pragma unroll
            for (int j = 0; j < GTN; j += 4) {
                float4 t4 = *(const float4*)&Bs[kk][tx * GTN + j];
                rb[j] = t4.x; rb[j + 1] = t4.y; rb[j + 2] = t4.z; rb[j + 3] = t4.w;
            }
            #pragma unroll
            for (int i = 0; i < GTM; i++)
                #pragma unroll
                for (int j = 0; j < GTN; j++)
                    acc[i][j] += ra[i] * rb[j];
        }
        __syncthreads();
    }

    #pragma unroll
    for (int i = 0; i < GTM; i++) {
        int row = bm + ty * GTM + i;
        float4* cr = (float4*)(C + (size_t)row * N + bn + tx * GTN);
        float4 v0 = {acc[i][0], acc[i][1], acc[i][2], acc[i][3]};
        float4 v1 = {acc[i][4], acc[i][5], acc[i][6], acc[i][7]};
        cr[0] = v0; cr[1] = v1;
    }
}

// ---------------------------------------------------------------------------
// Build u[BT,1536]: [z[t] + m1*z[t-1],  m2*z[t-2],  m3*z[t-3]]
// ---------------------------------------------------------------------------
__global__ __launch_bounds__(128)
void build_u(const float* __restrict__ z, const int* __restrict__ doc,
             float* __restrict__ u) {
    int t  = blockIdx.x;
    int tt = t & (TDIM - 1);
    int d0 = doc[t];
    bool m1 = (tt >= 1) && (doc[t - 1] == d0);
    bool m2 = (tt >= 2) && (doc[t - 2] == d0);
    bool m3 = (tt >= 3) && (doc[t - 3] == d0);

    const float4* z0 = (const float4*)(z + (size_t)t * DBDIM);
    const float4* z1 = (const float4*)(z + (size_t)(t - 1) * DBDIM);
    const float4* z2 = (const float4*)(z + (size_t)(t - 2) * DBDIM);
    const float4* z3 = (const float4*)(z + (size_t)(t - 3) * DBDIM);
    float4* up = (float4*)(u + (size_t)t * 1536);

    int i = threadIdx.x;                 // 128 threads, 128 float4 per block row
    float4 zero = make_float4(0.f, 0.f, 0.f, 0.f);

    float4 a = z0[i];
    if (m1) {
        float4 b = z1[i];
        a.x += b.x; a.y += b.y; a.z += b.z; a.w += b.w;
    }
    up[i]       = a;
    up[128 + i] = m2 ? z2[i] : zero;
    up[256 + i] = m3 ? z3[i] : zero;
}

// ---------------------------------------------------------------------------
// Gate + rms(out): per token t compute Σx², Σxk, Σk², Σv² over D=2048,
// gate = sigmoid(sign(g)*sqrt(max(|g|,1e-6))) with
//   g = Σxk * rsqrt(mean(x²)+eps) * rsqrt(mean(k²)+eps) / sqrt(D)
// normed = v * gate * rsqrt(gate²*mean(v²)+eps)
// ---------------------------------------------------------------------------
__global__ __launch_bounds__(256)
void gate_norm(const float* __restrict__ x, const float* __restrict__ k,
               const float* __restrict__ v, float* __restrict__ nrm) {
    int t = blockIdx.x;
    const float4* xp = (const float4*)(x + (size_t)t * DDIM);
    const float4* kp = (const float4*)(k + (size_t)t * DDIM);
    const float4* vp = (const float4*)(v + (size_t)t * DDIM);

    float sxx = 0.f, sxk = 0.f, skk = 0.f, svv = 0.f;
    float4 vreg[2];
    #pragma unroll
    for (int r = 0; r < 2; r++) {
        int i = threadIdx.x + r * 256;
        float4 xa = xp[i], ka = kp[i], va = vp[i];
        vreg[r] = va;
        sxx += xa.x * xa.x + xa.y * xa.y + xa.z * xa.z + xa.w * xa.w;
        sxk += xa.x * ka.x + xa.y * ka.y + xa.z * ka.z + xa.w * ka.w;
        skk += ka.x * ka.x + ka.y * ka.y + ka.z * ka.z + ka.w * ka.w;
        svv += va.x * va.x + va.y * va.y + va.z * va.z + va.w * va.w;
    }
    #pragma unroll
    for (int off = 16; off > 0; off >>= 1) {
        sxx += __shfl_down_sync(0xffffffffu, sxx, off);
        sxk += __shfl_down_sync(0xffffffffu, sxk, off);
        skk += __shfl_down_sync(0xffffffffu, skk, off);
        svv += __shfl_down_sync(0xffffffffu, svv, off);
    }
    __shared__ float sh[4][8];
    __shared__ float s_scale;
    int warp = threadIdx.x >> 5, lane = threadIdx.x & 31;
    if (lane == 0) {
        sh[0][warp] = sxx; sh[1][warp] = sxk; sh[2][warp] = skk; sh[3][warp] = svv;
    }
    __syncthreads();
    if (threadIdx.x == 0) {
        float a0 = 0.f, a1 = 0.f, a2 = 0.f, a3 = 0.f;
        #pragma unroll
        for (int w = 0; w < 8; w++) {
            a0 += sh[0][w]; a1 += sh[1][w]; a2 += sh[2][w]; a3 += sh[3][w];
        }
        const float invD = 1.0f / (float)DDIM;
        float g = a1 * rsqrtf(a0 * invD + EPSV) * rsqrtf(a2 * invD + EPSV)
                     * rsqrtf((float)DDIM);
        float sg = (g > 0.f) ? 1.f : ((g < 0.f) ? -1.f : 0.f);
        float gl = sg * sqrtf(fmaxf(fabsf(g), 1e-6f));
        float gate = 1.0f / (1.0f + expf(-gl));
        float mv = a3 * invD;
        s_scale = gate * rsqrtf(gate * gate * mv + EPSV);
    }
    __syncthreads();
    float sc = s_scale;
    float4* np = (float4*)(nrm + (size_t)t * DDIM);
    #pragma unroll
    for (int r = 0; r < 2; r++) {
        int i = threadIdx.x + r * 256;
        float4 va = vreg[r];
        va.x *= sc; va.y *= sc; va.z *= sc; va.w *= sc;
        np[i] = va;
    }
}

// ---------------------------------------------------------------------------
// Depthwise causal conv (K=4) with doc mask, then SiLU.
// res[t,d] = Σ_{s=0..3} normed[t-s,d] * mask_s * conv_w[d, 3-s]
// ---------------------------------------------------------------------------
__global__ __launch_bounds__(256)
void conv_silu(const float* __restrict__ nrm, const int* __restrict__ doc,
               const float* __restrict__ cw, float* __restrict__ out) {
    int t  = blockIdx.x;
    int tt = t & (TDIM - 1);
    int d0 = doc[t];
    bool m1 = (tt >= 1) && (doc[t - 1] == d0);
    bool m2 = (tt >= 2) && (doc[t - 2] == d0);
    bool m3 = (tt >= 3) && (doc[t - 3] == d0);

    const float* n0 = nrm + (size_t)t * DDIM;
    const float* n1 = nrm + (size_t)(t - 1) * DDIM;
    const float* n2 = nrm + (size_t)(t - 2) * DDIM;
    const float* n3 = nrm + (size_t)(t - 3) * DDIM;
    float4 zero = make_float4(0.f, 0.f, 0.f, 0.f);

    #pragma unroll
    for (int r = 0; r < 2; r++) {
        int d4 = threadIdx.x + r * 256;     // float4 index, 512 per token
        int d  = d4 * 4;
        float4 a0 = *(const float4*)(n0 + d);
        float4 a1 = m1 ? *(const float4*)(n1 + d) : zero;
        float4 a2 = m2 ? *(const float4*)(n2 + d) : zero;
        float4 a3 = m3 ? *(const float4*)(n3 + d) : zero;

        const float* p0 = (const float*)&a0;
        const float* p1 = (const float*)&a1;
        const float* p2 = (const float*)&a2;
        const float* p3 = (const float*)&a3;

        float4 o;
        float* po = (float*)&o;
        #pragma unroll
        for (int i = 0; i < 4; i++) {
            float4 w = *(const float4*)(cw + (size_t)(d + i) * 4); // taps [0..3]
            float res = p0[i] * w.w + p1[i] * w.z + p2[i] * w.y + p3[i] * w.x;
            po[i] = res / (1.0f + expf(-res));   // SiLU
        }
        *(float4*)(out + (size_t)t * DDIM + d) = o;
    }
}

// ---------------------------------------------------------------------------
extern "C" void kernel_launch(void* const* d_in, const int* in_sizes, int n_in,
                              void* d_out, int out_size) {
    const float* x      = (const float*)d_in[0];
    const int*   doc    = (const int*)  d_in[1];
    const float* W_in   = (const float*)d_in[2];
    const float* W_mix  = (const float*)d_in[3];
    const float* W_k    = (const float*)d_in[4];
    const float* W_v    = (const float*)d_in[5];
    const float* conv_w = (const float*)d_in[6];
    float* out = (float*)d_out;

    float *z, *u, *y, *k, *v, *n, *wc;
    cudaGetSymbolAddress((void**)&z,  g_z);
    cudaGetSymbolAddress((void**)&u,  g_u);
    cudaGetSymbolAddress((void**)&y,  g_y);
    cudaGetSymbolAddress((void**)&k,  g_k);
    cudaGetSymbolAddress((void**)&v,  g_v);
    cudaGetSymbolAddress((void**)&n,  g_n);
    cudaGetSymbolAddress((void**)&wc, g_wc);

    // 1) combined mix weights [512,1536]
    combine_wmix<<<(DBDIM * DBDIM + 255) / 256, 256>>>(W_mix, wc);

    // 2) z = x @ W_in^T : [16384,2048]x[512,2048]^T
    sgemm_nt<<<dim3(DBDIM / GBN, BT / GBM), 256>>>(x, W_in, z, BT, DBDIM, DDIM);

    // 3) shifted/masked feature assembly u[16384,1536]
    build_u<<<BT, 128>>>(z, doc, u);

    // 4) y = u @ Wcomb^T : [16384,1536]x[512,1536]^T
    sgemm_nt<<<dim3(DBDIM / GBN, BT / GBM), 256>>>(u, wc, y, BT, DBDIM, 3 * DBDIM);

    // 5) k = y @ W_k^T, v = y @ W_v^T : [16384,512]x[2048,512]^T
    sgemm_nt<<<dim3(DDIM / GBN, BT / GBM), 256>>>(y, W_k, k, BT, DDIM, DBDIM);
    sgemm_nt<<<dim3(DDIM / GBN, BT / GBM), 256>>>(y, W_v, v, BT, DDIM, DBDIM);

    // 6) gate + rms-norm of gated output
    gate_norm<<<BT, 256>>>(x, k, v, n);

    // 7) depthwise causal conv + SiLU -> final output
    conv_silu<<<BT, 256>>>(n, doc, conv_w, out);
}

// round 4
// speedup vs baseline: 3.0302x; 3.0302x over previous
#include <cuda_runtime.h>
#include <cstdint>
#include <math.h>

// Problem constants
#define BDIM   4
#define TDIM   4096
#define DDIM   2048
#define DBDIM  512
#define BT     (BDIM * TDIM)   // 16384 tokens
#define EPSV   1e-6f

// ---------------- scratch (static device globals; no runtime allocation) ----
__device__ float g_xc  [(size_t)BT * DDIM];        // tf32-rounded x
__device__ float g_winc[(size_t)DBDIM * DDIM];     // tf32-rounded W_in
__device__ float g_wkc [(size_t)DDIM * DBDIM];     // tf32-rounded W_k
__device__ float g_wvc [(size_t)DDIM * DBDIM];     // tf32-rounded W_v
__device__ float g_z   [(size_t)BT * DBDIM];
__device__ float g_u   [(size_t)BT * 3 * DBDIM];
__device__ float g_y   [(size_t)BT * DBDIM];
__device__ float g_k   [(size_t)BT * DDIM];
__device__ float g_v   [(size_t)BT * DDIM];
__device__ float g_n   [(size_t)BT * DDIM];
__device__ float g_wc  [(size_t)DBDIM * 3 * DBDIM];

// ---------------------------------------------------------------------------
// helpers
// ---------------------------------------------------------------------------
__device__ __forceinline__ float tf32r(float x) {
    uint32_t r;                                    // tf32 dest must be .b32
    asm("cvt.rna.tf32.f32 %0, %1;" : "=r"(r) : "f"(x));
    return __uint_as_float(r);
}

__device__ __forceinline__ uint32_t s2u(const void* p) {
    uint32_t a;
    asm("{ .reg .u64 t; cvta.to.shared.u64 t, %1; cvt.u32.u64 %0, t; }"
        : "=r"(a) : "l"(p));
    return a;
}

__device__ __forceinline__ void cp16(uint32_t dst, const void* src) {
    asm volatile("cp.async.cg.shared.global [%0], [%1], 16;" :: "r"(dst), "l"(src));
}
__device__ __forceinline__ void cp_commit() {
    asm volatile("cp.async.commit_group;" ::: "memory");
}
template<int N> __device__ __forceinline__ void cp_wait() {
    asm volatile("cp.async.wait_group %0;" :: "n"(N) : "memory");
}

__device__ __forceinline__ uint32_t lds_u32(uint32_t addr) {
    uint32_t v;
    asm volatile("ld.shared.b32 %0, [%1];" : "=r"(v) : "r"(addr));
    return v;
}

// mma.sync m16n8k8 tf32 (legacy tensor path, valid on compute_100)
__device__ __forceinline__ void mma_tf32(float& c0, float& c1, float& c2, float& c3,
                                         uint32_t a0, uint32_t a1, uint32_t a2,
                                         uint32_t a3, uint32_t b0, uint32_t b1) {
    asm volatile(
        "mma.sync.aligned.m16n8k8.row.col.f32.tf32.tf32.f32 "
        "{%0,%1,%2,%3}, {%4,%5,%6,%7}, {%8,%9}, {%0,%1,%2,%3};"
        : "+f"(c0), "+f"(c1), "+f"(c2), "+f"(c3)
        : "r"(a0), "r"(a1), "r"(a2), "r"(a3), "r"(b0), "r"(b1));
}

// ---------------------------------------------------------------------------
// TF32 tensor-core NT GEMM: C[M,N] = A[M,K] * W[N,K]^T, fp32 accumulate.
// 128x128x32 block tile, 8 warps (4m x 2n), warp tile 32x64, 3-stage cp.async.
// SMEM rows padded to 36 floats (144B) -> conflict-free mma fragment loads.
// ---------------------------------------------------------------------------
#define TBM    128
#define TBN    128
#define TBK    32
#define NSTG   3
#define LROW   36                       // padded row stride (floats)
#define STG_B  (128 * LROW * 4)         // 18432 bytes per operand per stage
#define SOFF_B (NSTG * STG_B)           // B region after A region
#define GEMM_SMEM (2 * NSTG * STG_B)    // 110592 bytes

template<bool RTF32>
__global__ void __launch_bounds__(256, 2)
gemm_tc(const float* __restrict__ A, const float* __restrict__ W,
        float* __restrict__ C, int M, int N, int K) {
    extern __shared__ __align__(16) char smem[];
    const uint32_t sb = s2u(smem);

    const int tid  = threadIdx.x;
    const int lane = tid & 31;
    const int wid  = tid >> 5;
    const int wm   = (wid & 3) * 32;      // warp row offset in tile
    const int wn   = (wid >> 2) * 64;     // warp col offset in tile
    const int g    = lane >> 2;           // groupID 0..7
    const int tg   = lane & 3;            // thread-in-group 0..3

    const int bm = blockIdx.y * TBM;
    const int bn = blockIdx.x * TBN;
    const int num_k = K / TBK;

    const float* Abase = A + (size_t)bm * K;
    const float* Wbase = W + (size_t)bn * K;

    auto load_stage = [&](int ks, int buf) {
        const float* Ap = Abase + ks * TBK;
        const float* Wp = Wbase + ks * TBK;
        uint32_t ab = sb + buf * STG_B;
        uint32_t bb = sb + SOFF_B + buf * STG_B;
        #pragma unroll
        for (int i = 0; i < 4; i++) {             // 1024 16B chunks / 256 thr
            int idx = tid + i * 256;
            int r = idx >> 3, c4 = idx & 7;
            cp16(ab + r * (LROW * 4) + c4 * 16, Ap + (size_t)r * K + c4 * 4);
        }
        #pragma unroll
        for (int i = 0; i < 4; i++) {
            int idx = tid + i * 256;
            int r = idx >> 3, c4 = idx & 7;
            cp16(bb + r * (LROW * 4) + c4 * 16, Wp + (size_t)r * K + c4 * 4);
        }
        cp_commit();
    };

    float acc[2][8][4];
    #pragma unroll
    for (int mi = 0; mi < 2; mi++)
        #pragma unroll
        for (int ni = 0; ni < 8; ni++)
            #pragma unroll
            for (int c = 0; c < 4; c++) acc[mi][ni][c] = 0.f;

    // prologue: 2 stages in flight
    load_stage(0, 0);
    load_stage(1, 1);

    for (int k = 0; k < num_k; k++) {
        cp_wait<NSTG - 2>();
        __syncthreads();                 // stage k ready; stage (k+2)%3 free

        int kn = k + 2;
        if (kn < num_k) load_stage(kn, kn % NSTG); else cp_commit();

        uint32_t ab = sb + (k % NSTG) * STG_B;
        uint32_t bb = sb + SOFF_B + (k % NSTG) * STG_B;

        #pragma unroll
        for (int ks = 0; ks < 4; ks++) {         // 4 x k8 slices
            const int kk = ks * 8;
            uint32_t af[2][4], bf[8][2];
            #pragma unroll
            for (int mi = 0; mi < 2; mi++) {
                int r0 = wm + mi * 16 + g;
                uint32_t base0 = ab + (r0)     * (LROW * 4) + (kk + tg) * 4;
                uint32_t base1 = ab + (r0 + 8) * (LROW * 4) + (kk + tg) * 4;
                af[mi][0] = lds_u32(base0);
                af[mi][1] = lds_u32(base1);
                af[mi][2] = lds_u32(base0 + 16);
                af[mi][3] = lds_u32(base1 + 16);
            }
            #pragma unroll
            for (int ni = 0; ni < 8; ni++) {
                int n0 = wn + ni * 8 + g;
                uint32_t base = bb + n0 * (LROW * 4) + (kk + tg) * 4;
                bf[ni][0] = lds_u32(base);
                bf[ni][1] = lds_u32(base + 16);
            }
            #pragma unroll
            for (int mi = 0; mi < 2; mi++)
                #pragma unroll
                for (int ni = 0; ni < 8; ni++)
                    mma_tf32(acc[mi][ni][0], acc[mi][ni][1],
                             acc[mi][ni][2], acc[mi][ni][3],
                             af[mi][0], af[mi][1], af[mi][2], af[mi][3],
                             bf[ni][0], bf[ni][1]);
        }
    }

    // epilogue: direct float2 stores
    #pragma unroll
    for (int mi = 0; mi < 2; mi++) {
        #pragma unroll
        for (int ni = 0; ni < 8; ni++) {
            int row = bm + wm + mi * 16 + g;
            int col = bn + wn + ni * 8 + tg * 2;
            float v0 = acc[mi][ni][0], v1 = acc[mi][ni][1];
            float v2 = acc[mi][ni][2], v3 = acc[mi][ni][3];
            if (RTF32) { v0 = tf32r(v0); v1 = tf32r(v1);
                         v2 = tf32r(v2); v3 = tf32r(v3); }
            *(float2*)(C + (size_t)row * N + col)       = make_float2(v0, v1);
            *(float2*)(C + (size_t)(row + 8) * N + col) = make_float2(v2, v3);
        }
    }
}

// ---------------------------------------------------------------------------
// tf32 rounding copy
// ---------------------------------------------------------------------------
__global__ void round_copy(const float* __restrict__ src, float* __restrict__ dst,
                           int n4) {
    for (int i = blockIdx.x * blockDim.x + threadIdx.x; i < n4;
         i += gridDim.x * blockDim.x) {
        float4 v = ((const float4*)src)[i];
        v.x = tf32r(v.x); v.y = tf32r(v.y); v.z = tf32r(v.z); v.w = tf32r(v.w);
        ((float4*)dst)[i] = v;
    }
}

// ---------------------------------------------------------------------------
// Combine W_mix into Wcomb[512,1536] (tf32 rounded)
// ---------------------------------------------------------------------------
__global__ void combine_wmix(const float* __restrict__ wmix, float* __restrict__ wc) {
    int idx = blockIdx.x * blockDim.x + threadIdx.x;
    if (idx >= DBDIM * DBDIM) return;
    int f = idx / DBDIM, e = idx % DBDIM;
    float w2 = wmix[0 * DBDIM * DBDIM + idx];
    float w3 = wmix[1 * DBDIM * DBDIM + idx];
    float w4 = wmix[2 * DBDIM * DBDIM + idx];
    const float c2 = 1.0f / 6.0f, c3 = 1.0f / 9.0f, c4 = 1.0f / 12.0f;
    wc[(size_t)f * 1536 + e]        = tf32r(w2 * c2 + w3 * c3 + w4 * c4);
    wc[(size_t)f * 1536 + 512 + e]  = tf32r(w3 * c3 + w4 * c4);
    wc[(size_t)f * 1536 + 1024 + e] = tf32r(w4 * c4);
}

// ---------------------------------------------------------------------------
// Build u[BT,1536] (tf32 rounded)
// ---------------------------------------------------------------------------
__global__ void __launch_bounds__(128)
build_u(const float* __restrict__ z, const int* __restrict__ doc,
        float* __restrict__ u) {
    int t  = blockIdx.x;
    int tt = t & (TDIM - 1);
    int d0 = doc[t];
    bool m1 = (tt >= 1) && (doc[t - 1] == d0);
    bool m2 = (tt >= 2) && (doc[t - 2] == d0);
    bool m3 = (tt >= 3) && (doc[t - 3] == d0);

    const float4* z0 = (const float4*)(z + (size_t)t * DBDIM);
    const float4* z1 = (const float4*)(z + (size_t)(t - 1) * DBDIM);
    const float4* z2 = (const float4*)(z + (size_t)(t - 2) * DBDIM);
    const float4* z3 = (const float4*)(z + (size_t)(t - 3) * DBDIM);
    float4* up = (float4*)(u + (size_t)t * 1536);

    int i = threadIdx.x;
    float4 zero = make_float4(0.f, 0.f, 0.f, 0.f);

    float4 a = z0[i];
    if (m1) {
        float4 b = z1[i];
        a.x += b.x; a.y += b.y; a.z += b.z; a.w += b.w;
    }
    a.x = tf32r(a.x); a.y = tf32r(a.y); a.z = tf32r(a.z); a.w = tf32r(a.w);
    up[i]       = a;
    up[128 + i] = m2 ? z2[i] : zero;   // z already tf32-rounded by GEMM epilogue
    up[256 + i] = m3 ? z3[i] : zero;
}

// ---------------------------------------------------------------------------
// Gate + rms(out)
// ---------------------------------------------------------------------------
__global__ void __launch_bounds__(256)
gate_norm(const float* __restrict__ x, const float* __restrict__ k,
          const float* __restrict__ v, float* __restrict__ nrm) {
    int t = blockIdx.x;
    const float4* xp = (const float4*)(x + (size_t)t * DDIM);
    const float4* kp = (const float4*)(k + (size_t)t * DDIM);
    const float4* vp = (const float4*)(v + (size_t)t * DDIM);

    float sxx = 0.f, sxk = 0.f, skk = 0.f, svv = 0.f;
    float4 vreg[2];
    #pragma unroll
    for (int r = 0; r < 2; r++) {
        int i = threadIdx.x + r * 256;
        float4 xa = xp[i], ka = kp[i], va = vp[i];
        vreg[r] = va;
        sxx += xa.x * xa.x + xa.y * xa.y + xa.z * xa.z + xa.w * xa.w;
        sxk += xa.x * ka.x + xa.y * ka.y + xa.z * ka.z + xa.w * ka.w;
        skk += ka.x * ka.x + ka.y * ka.y + ka.z * ka.z + ka.w * ka.w;
        svv += va.x * va.x + va.y * va.y + va.z * va.z + va.w * va.w;
    }
    #pragma unroll
    for (int off = 16; off > 0; off >>= 1) {
        sxx += __shfl_down_sync(0xffffffffu, sxx, off);
        sxk += __shfl_down_sync(0xffffffffu, sxk, off);
        skk += __shfl_down_sync(0xffffffffu, skk, off);
        svv += __shfl_down_sync(0xffffffffu, svv, off);
    }
    __shared__ float sh[4][8];
    __shared__ float s_scale;
    int warp = threadIdx.x >> 5, lane = threadIdx.x & 31;
    if (lane == 0) {
        sh[0][warp] = sxx; sh[1][warp] = sxk; sh[2][warp] = skk; sh[3][warp] = svv;
    }
    __syncthreads();
    if (threadIdx.x == 0) {
        float a0 = 0.f, a1 = 0.f, a2 = 0.f, a3 = 0.f;
        #pragma unroll
        for (int w = 0; w < 8; w++) {
            a0 += sh[0][w]; a1 += sh[1][w]; a2 += sh[2][w]; a3 += sh[3][w];
        }
        const float invD = 1.0f / (float)DDIM;
        float g = a1 * rsqrtf(a0 * invD + EPSV) * rsqrtf(a2 * invD + EPSV)
                     * rsqrtf((float)DDIM);
        float sg = (g > 0.f) ? 1.f : ((g < 0.f) ? -1.f : 0.f);
        float gl = sg * sqrtf(fmaxf(fabsf(g), 1e-6f));
        float gate = 1.0f / (1.0f + expf(-gl));
        float mv = a3 * invD;
        s_scale = gate * rsqrtf(gate * gate * mv + EPSV);
    }
    __syncthreads();
    float sc = s_scale;
    float4* np = (float4*)(nrm + (size_t)t * DDIM);
    #pragma unroll
    for (int r = 0; r < 2; r++) {
        int i = threadIdx.x + r * 256;
        float4 va = vreg[r];
        va.x *= sc; va.y *= sc; va.z *= sc; va.w *= sc;
        np[i] = va;
    }
}

// ---------------------------------------------------------------------------
// Depthwise causal conv (K=4) + SiLU
// ---------------------------------------------------------------------------
__global__ void __launch_bounds__(256)
conv_silu(const float* __restrict__ nrm, const int* __restrict__ doc,
          const float* __restrict__ cw, float* __restrict__ out) {
    int t  = blockIdx.x;
    int tt = t & (TDIM - 1);
    int d0 = doc[t];
    bool m1 = (tt >= 1) && (doc[t - 1] == d0);
    bool m2 = (tt >= 2) && (doc[t - 2] == d0);
    bool m3 = (tt >= 3) && (doc[t - 3] == d0);

    const float* n0 = nrm + (size_t)t * DDIM;
    const float* n1 = nrm + (size_t)(t - 1) * DDIM;
    const float* n2 = nrm + (size_t)(t - 2) * DDIM;
    const float* n3 = nrm + (size_t)(t - 3) * DDIM;
    float4 zero = make_float4(0.f, 0.f, 0.f, 0.f);

    #pragma unroll
    for (int r = 0; r < 2; r++) {
        int d4 = threadIdx.x + r * 256;
        int d  = d4 * 4;
        float4 a0 = *(const float4*)(n0 + d);
        float4 a1 = m1 ? *(const float4*)(n1 + d) : zero;
        float4 a2 = m2 ? *(const float4*)(n2 + d) : zero;
        float4 a3 = m3 ? *(const float4*)(n3 + d) : zero;

        const float* p0 = (const float*)&a0;
        const float* p1 = (const float*)&a1;
        const float* p2 = (const float*)&a2;
        const float* p3 = (const float*)&a3;

        float4 o;
        float* po = (float*)&o;
        #pragma unroll
        for (int i = 0; i < 4; i++) {
            float4 w = *(const float4*)(cw + (size_t)(d + i) * 4);
            float res = p0[i] * w.w + p1[i] * w.z + p2[i] * w.y + p3[i] * w.x;
            po[i] = res / (1.0f + expf(-res));
        }
        *(float4*)(out + (size_t)t * DDIM + d) = o;
    }
}

// ---------------------------------------------------------------------------
extern "C" void kernel_launch(void* const* d_in, const int* in_sizes, int n_in,
                              void* d_out, int out_size) {
    const float* x      = (const float*)d_in[0];
    const int*   doc    = (const int*)  d_in[1];
    const float* W_in   = (const float*)d_in[2];
    const float* W_mix  = (const float*)d_in[3];
    const float* W_k    = (const float*)d_in[4];
    const float* W_v    = (const float*)d_in[5];
    const float* conv_w = (const float*)d_in[6];
    float* out = (float*)d_out;

    float *xc, *winc, *wkc, *wvc, *z, *u, *y, *k, *v, *n, *wc;
    cudaGetSymbolAddress((void**)&xc,   g_xc);
    cudaGetSymbolAddress((void**)&winc, g_winc);
    cudaGetSymbolAddress((void**)&wkc,  g_wkc);
    cudaGetSymbolAddress((void**)&wvc,  g_wvc);
    cudaGetSymbolAddress((void**)&z,    g_z);
    cudaGetSymbolAddress((void**)&u,    g_u);
    cudaGetSymbolAddress((void**)&y,    g_y);
    cudaGetSymbolAddress((void**)&k,    g_k);
    cudaGetSymbolAddress((void**)&v,    g_v);
    cudaGetSymbolAddress((void**)&n,    g_n);
    cudaGetSymbolAddress((void**)&wc,   g_wc);

    cudaFuncSetAttribute(gemm_tc<true>,
                         cudaFuncAttributeMaxDynamicSharedMemorySize, GEMM_SMEM);
    cudaFuncSetAttribute(gemm_tc<false>,
                         cudaFuncAttributeMaxDynamicSharedMemorySize, GEMM_SMEM);

    // tf32-rounded operand copies
    round_copy<<<2048, 256>>>(x,    xc,   BT * DDIM / 4);
    round_copy<<<512,  256>>>(W_in, winc, DBDIM * DDIM / 4);
    round_copy<<<512,  256>>>(W_k,  wkc,  DDIM * DBDIM / 4);
    round_copy<<<512,  256>>>(W_v,  wvc,  DDIM * DBDIM / 4);
    combine_wmix<<<(DBDIM * DBDIM + 255) / 256, 256>>>(W_mix, wc);

    // z = xc @ winc^T : [16384,2048] x [512,2048]^T  (tf32 epilogue round)
    gemm_tc<true><<<dim3(DBDIM / TBN, BT / TBM), 256, GEMM_SMEM>>>(
        xc, winc, z, BT, DBDIM, DDIM);

    // u assembly (tf32 rounded)
    build_u<<<BT, 128>>>(z, doc, u);

    // y = u @ wc^T : [16384,1536] x [512,1536]^T (tf32 epilogue round)
    gemm_tc<true><<<dim3(DBDIM / TBN, BT / TBM), 256, GEMM_SMEM>>>(
        u, wc, y, BT, DBDIM, 3 * DBDIM);

    // k = y @ wkc^T, v = y @ wvc^T : [16384,512] x [2048,512]^T
    gemm_tc<false><<<dim3(DDIM / TBN, BT / TBM), 256, GEMM_SMEM>>>(
        y, wkc, k, BT, DDIM, DBDIM);
    gemm_tc<false><<<dim3(DDIM / TBN, BT / TBM), 256, GEMM_SMEM>>>(
        y, wvc, v, BT, DDIM, DBDIM);

    // gate + rms-norm of gated output
    gate_norm<<<BT, 256>>>(x, k, v, n);

    // depthwise causal conv + SiLU -> final output
    conv_silu<<<BT, 256>>>(n, doc, conv_w, out);
}